// round 10
// baseline (speedup 1.0000x reference)
#include <cuda_runtime.h>
#include <math.h>
#include <stdint.h>

// Problem constants
#define TT 512
#define BB 64
#define VV 256
#define HH 1024
#define NCTA 64

// ---------------------------------------------------------------------------
// Static device state (allocation-free rule). Everything fp32, original layouts.
// ---------------------------------------------------------------------------
__device__ float g_hf[3][2][BB * HH];           // ping-pong hidden, fp32
__device__ float g_cf[3][BB * HH];              // cell state, fp32
__device__ float g_yT[(size_t)BB * HH * TT];    // masked top-layer h: [b][u][t]
__device__ unsigned g_bar_cnt;
__device__ unsigned g_bar_gen;

struct Params {
    const float* inputs;   // [T][B][V] one-hot fp32
    const int*   lengths;  // [B]
    const float *Wih0, *Whh0, *bih0, *bhh0;     // [4H,V] [4H,H] [4H] [4H]
    const float *Wihr, *Whhr, *bihr, *bhhr;     // [2,4H,H] [2,4H,H] [2,4H] [2,4H]
    const float *Wout, *bout;                   // [V,H] [V]
};

__device__ __forceinline__ float sigf(float x) { return 1.0f / (1.0f + expf(-x)); }

// Grid barrier (64 co-resident CTAs): release via atomicExch, spin via L2 atomic.
__device__ __forceinline__ void grid_bar(unsigned target) {
    __syncthreads();
    if (threadIdx.x == 0) {
        __threadfence();
        unsigned old = atomicAdd(&g_bar_cnt, 1u);
        if (old == NCTA - 1) {
            g_bar_cnt = 0;
            __threadfence();
            atomicExch(&g_bar_gen, target);
        } else {
            while (atomicAdd(&g_bar_gen, 0u) != target) {}
        }
        __threadfence();
    }
    __syncthreads();
}

__global__ void init_kernel() {
    int i = blockIdx.x * blockDim.x + threadIdx.x;
    float* h = (float*)g_hf;
    float* c = (float*)g_cf;
    for (int k = i; k < 3 * 2 * BB * HH; k += gridDim.x * blockDim.x) h[k] = 0.0f;
    for (int k = i; k < 3 * BB * HH;     k += gridDim.x * blockDim.x) c[k] = 0.0f;
    if (i == 0) { g_bar_cnt = 0; g_bar_gen = 0; }
}

// ---------------------------------------------------------------------------
// Persistent LSTM: 64 CTAs x 256 threads. CTA nblk owns units uu = nblk*16+0..15.
// Thread (tx,ty): unit u = tx (0..15), batches b = ty*4..ty*4+3. Each thread
// accumulates ALL FOUR gates of its unit for its 4 batches -> no regroup stage.
// GEMM: K-chunked (64) through smem, weights read directly from input buffers.
// Cross-SM h traffic via __ldcg/__stcg (L2-coherent inside persistent kernel).
// ---------------------------------------------------------------------------
__global__ void __launch_bounds__(256, 1) lstm_persistent(Params p) {
    __shared__ float As[64 * 68];   // [batch][k]  (chunk of activations)
    __shared__ float Ws[64 * 68];   // [jj=G*16+u][k] (chunk of weights)

    const int tid  = threadIdx.x;
    const int nblk = blockIdx.x;
    const int tx = tid & 15, ty = tid >> 4;
    const int b0 = ty * 4;
    const int lrow = tid >> 2, lq = tid & 3;   // load map: row 0..63, quarter 0..3
    const int uu = nblk * 16 + tx;
    // W row for the load map's jj = lrow: r = G*1024 + nblk*16 + u
    const int rload = (lrow >> 4) * HH + nblk * 16 + (lrow & 15);

    // Biases (constant over t): bias[l][G] for this thread's unit uu.
    float bias[3][4];
#pragma unroll
    for (int G = 0; G < 4; G++) {
        bias[0][G] = p.bih0[G * HH + uu] + p.bhh0[G * HH + uu];
        bias[1][G] = p.bihr[G * HH + uu] + p.bhhr[G * HH + uu];
        bias[2][G] = p.bihr[4 * HH + G * HH + uu] + p.bhhr[4 * HH + G * HH + uu];
    }
    int len[4];
#pragma unroll
    for (int i = 0; i < 4; i++) len[i] = p.lengths[b0 + i];

    unsigned target = 0;

    for (int t = 0; t < TT; t++) {
        const int pin = t & 1, pout = pin ^ 1;
        for (int l = 0; l < 3; l++) {
            // Sources for the concatenated K dimension [x | h_prev]
            const float *A0, *A1, *W0, *W1;
            int astr0, w0str, split, nch;
            if (l == 0) {
                A0 = p.inputs + (size_t)t * BB * VV; astr0 = VV;  // one-hot x_t
                A1 = g_hf[0][pin];
                W0 = p.Wih0; w0str = VV; W1 = p.Whh0;
                split = VV; nch = (VV + HH) / 64;                 // 20
            } else if (l == 1) {
                A0 = g_hf[0][pout]; astr0 = HH;                   // lower h, this step
                A1 = g_hf[1][pin];
                W0 = p.Wihr; w0str = HH; W1 = p.Whhr;
                split = HH; nch = 32;
            } else {
                A0 = g_hf[1][pout]; astr0 = HH;
                A1 = g_hf[2][pin];
                W0 = p.Wihr + (size_t)4 * HH * HH; w0str = HH;
                W1 = p.Whhr + (size_t)4 * HH * HH;
                split = HH; nch = 32;
            }

            float acc[4][4];
#pragma unroll
            for (int i = 0; i < 4; i++)
#pragma unroll
                for (int G = 0; G < 4; G++) acc[i][G] = 0.0f;

            float4 apre[4], wpre[4];
            auto fetch = [&](int c) {
                int k0 = c * 64;
                const float* Ab; const float* Wb; int as, ws, kk;
                if (k0 < split) { Ab = A0; as = astr0; Wb = W0; ws = w0str; kk = k0; }
                else            { Ab = A1; as = HH;    Wb = W1; ws = HH;    kk = k0 - split; }
                const float* ar = Ab + (size_t)lrow * as + kk + lq * 16;
                const float* wr = Wb + (size_t)rload * ws + kk + lq * 16;
#pragma unroll
                for (int i = 0; i < 4; i++) {
                    apre[i] = __ldcg((const float4*)(ar + i * 4));  // L2-coherent
                    wpre[i] = __ldg((const float4*)(wr + i * 4));   // immutable
                }
            };
            auto stash = [&]() {
#pragma unroll
                for (int i = 0; i < 4; i++) {
                    *(float4*)&As[lrow * 68 + lq * 16 + i * 4] = apre[i];
                    *(float4*)&Ws[lrow * 68 + lq * 16 + i * 4] = wpre[i];
                }
            };

            fetch(0);
            for (int c = 0; c < nch; c++) {
                stash();
                __syncthreads();
                if (c + 1 < nch) fetch(c + 1);
#pragma unroll
                for (int k4 = 0; k4 < 16; k4++) {
                    float4 av[4], wv[4];
#pragma unroll
                    for (int i = 0; i < 4; i++)
                        av[i] = *(const float4*)&As[(b0 + i) * 68 + k4 * 4];
#pragma unroll
                    for (int G = 0; G < 4; G++)
                        wv[G] = *(const float4*)&Ws[(G * 16 + tx) * 68 + k4 * 4];
#pragma unroll
                    for (int i = 0; i < 4; i++)
#pragma unroll
                        for (int G = 0; G < 4; G++)
                            acc[i][G] += av[i].x * wv[G].x + av[i].y * wv[G].y +
                                         av[i].z * wv[G].z + av[i].w * wv[G].w;
                }
                __syncthreads();
            }

            // LSTM cell pointwise — gates already complete in registers.
            float* cst  = g_cf[l];
            float* hout = g_hf[l][pout];
#pragma unroll
            for (int i = 0; i < 4; i++) {
                int b = b0 + i;
                size_t ci = (size_t)b * HH + uu;
                float ii = acc[i][0] + bias[l][0];
                float ff = acc[i][1] + bias[l][1];
                float gg = acc[i][2] + bias[l][2];
                float oo = acc[i][3] + bias[l][3];
                float cn = sigf(ff) * cst[ci] + sigf(ii) * tanhf(gg);
                float hn = sigf(oo) * tanhf(cn);
                cst[ci] = cn;
                __stcg(&hout[ci], hn);                       // L2-visible for peers
                if (l == 2)
                    g_yT[ci * TT + t] = (t < len[i]) ? hn : 0.0f;  // mask output only
            }
            grid_bar(++target);
        }
    }
}

// ---------------------------------------------------------------------------
// Projection: out[b][v][t] = sum_u Wout[v][u] * yT[b][u][t] + bout[v]
// Plain fp32 tiled GEMM. CTA tile: 32 v x 64 t for one batch. Grid 64*8*8.
// ---------------------------------------------------------------------------
__global__ void __launch_bounds__(256, 1) proj_kernel(Params p, float* __restrict__ out) {
    __shared__ float Wv[32 * 68];   // [v][k]
    __shared__ float Yt[64 * 68];   // [k][t]

    const int blk = blockIdx.x;
    const int b  = blk >> 6;        // 0..63
    const int vt = (blk >> 3) & 7;  // 0..7
    const int tt = blk & 7;         // 0..7
    const int tid = threadIdx.x;

    const int yrow = tid >> 2, yq = tid & 3;   // Y tile loads: 64k x 64t
    const int wrow = tid >> 3, wq = tid & 7;   // W tile loads: 32v x 64k
    const int vr = tid >> 5;                   // 0..7 -> 4 v's
    const int tc = tid & 31;                   // 0..31 -> 2 t's

    float acc[4][2];
#pragma unroll
    for (int j = 0; j < 4; j++) { acc[j][0] = 0.0f; acc[j][1] = 0.0f; }

    const float* ybase = g_yT + (size_t)b * HH * TT;
    float4 ypre[4], wpre[2];
    auto fetch = [&](int c) {
        int k0 = c * 64;
        const float* yr = ybase + (size_t)(k0 + yrow) * TT + tt * 64 + yq * 16;
#pragma unroll
        for (int i = 0; i < 4; i++) ypre[i] = *(const float4*)(yr + i * 4);
        const float* wr = p.Wout + (size_t)(vt * 32 + wrow) * HH + k0 + wq * 8;
#pragma unroll
        for (int i = 0; i < 2; i++) wpre[i] = *(const float4*)(wr + i * 4);
    };
    auto stash = [&]() {
#pragma unroll
        for (int i = 0; i < 4; i++) *(float4*)&Yt[yrow * 68 + yq * 16 + i * 4] = ypre[i];
#pragma unroll
        for (int i = 0; i < 2; i++) *(float4*)&Wv[wrow * 68 + wq * 8 + i * 4] = wpre[i];
    };

    fetch(0);
    for (int c = 0; c < 16; c++) {
        stash();
        __syncthreads();
        if (c + 1 < 16) fetch(c + 1);
#pragma unroll 8
        for (int k = 0; k < 64; k++) {
            float y0 = Yt[k * 68 + tc * 2];
            float y1 = Yt[k * 68 + tc * 2 + 1];
#pragma unroll
            for (int j = 0; j < 4; j++) {
                float w = Wv[(vr * 4 + j) * 68 + k];
                acc[j][0] += w * y0;
                acc[j][1] += w * y1;
            }
        }
        __syncthreads();
    }

#pragma unroll
    for (int j = 0; j < 4; j++) {
        int v = vt * 32 + vr * 4 + j;
        float bo = p.bout[v];
        size_t o = ((size_t)b * VV + v) * TT + tt * 64 + tc * 2;
        out[o]     = acc[j][0] + bo;
        out[o + 1] = acc[j][1] + bo;
    }
}

// ---------------------------------------------------------------------------
// Launch: 3 graph nodes. Inputs resolved defensively by element count
// (unique sizes by value; ties broken by order of appearance = dict order).
// ---------------------------------------------------------------------------
extern "C" void kernel_launch(void* const* d_in, const int* in_sizes, int n_in,
                              void* d_out, int out_size) {
    Params p = {};
    int nbig = 0, n4k = 0, n8k = 0;
    for (int i = 0; i < n_in; i++) {
        const void* ptr = d_in[i];
        switch (in_sizes[i]) {
            case 8388608:  // inputs (T*B*V) / Wih_rest / Whh_rest — in dict order
                if (nbig == 0)      p.inputs = (const float*)ptr;
                else if (nbig == 1) p.Wihr   = (const float*)ptr;
                else                p.Whhr   = (const float*)ptr;
                nbig++; break;
            case 64:      p.lengths = (const int*)ptr;   break;
            case 1048576: p.Wih0    = (const float*)ptr; break;
            case 4194304: p.Whh0    = (const float*)ptr; break;
            case 4096:
                if (n4k == 0) p.bih0 = (const float*)ptr; else p.bhh0 = (const float*)ptr;
                n4k++; break;
            case 8192:
                if (n8k == 0) p.bihr = (const float*)ptr; else p.bhhr = (const float*)ptr;
                n8k++; break;
            case 262144:  p.Wout = (const float*)ptr; break;
            case 256:     p.bout = (const float*)ptr; break;
            default: break;
        }
    }

    init_kernel<<<256, 256>>>();
    lstm_persistent<<<NCTA, 256>>>(p);
    proj_kernel<<<64 * 8 * 8, 256>>>(p, (float*)d_out);
}

// round 11
// speedup vs baseline: 2.3707x; 2.3707x over previous
#include <cuda_runtime.h>
#include <cuda_fp16.h>
#include <math.h>
#include <stdint.h>

// Problem constants
#define TT 512
#define BB 64
#define VV 256
#define HH 1024
#define NCTA 128

// ---------------------------------------------------------------------------
// Static device state (allocation-free rule). fp32 h state, original layouts.
// ---------------------------------------------------------------------------
__device__ float g_hf[3][2][BB * HH];           // ping-pong hidden, fp32
__device__ float g_yT[(size_t)BB * HH * TT];    // masked top-layer h: [b][u][t]
__device__ unsigned g_bar_cnt;
__device__ unsigned g_bar_gen;

struct Params {
    const float* inputs;   // [T][B][V] one-hot fp32
    const int*   lengths;  // [B]
    const float *Wih0, *Whh0, *bih0, *bhh0;     // [4H,V] [4H,H] [4H] [4H]
    const float *Wihr, *Whhr, *bihr, *bhhr;     // [2,4H,H] [2,4H,H] [2,4H] [2,4H]
    const float *Wout, *bout;                   // [V,H] [V]
};

__device__ __forceinline__ float sigf(float x) { return 1.0f / (1.0f + expf(-x)); }

__device__ __forceinline__ void mma16816(float* d, const uint32_t* a, const uint32_t* b) {
    asm volatile(
        "mma.sync.aligned.m16n8k16.row.col.f32.f16.f16.f32 "
        "{%0,%1,%2,%3}, {%4,%5,%6,%7}, {%8,%9}, {%0,%1,%2,%3};\n"
        : "+f"(d[0]), "+f"(d[1]), "+f"(d[2]), "+f"(d[3])
        : "r"(a[0]), "r"(a[1]), "r"(a[2]), "r"(a[3]), "r"(b[0]), "r"(b[1]));
}

// Grid barrier (128 co-resident CTAs) — R10-validated pattern.
__device__ __forceinline__ void grid_bar(unsigned target) {
    __syncthreads();
    if (threadIdx.x == 0) {
        __threadfence();
        unsigned old = atomicAdd(&g_bar_cnt, 1u);
        if (old == NCTA - 1) {
            g_bar_cnt = 0;
            __threadfence();
            atomicExch(&g_bar_gen, target);
        } else {
            while (atomicAdd(&g_bar_gen, 0u) != target) {}
        }
        __threadfence();
    }
    __syncthreads();
}

__global__ void init_kernel() {
    int i = blockIdx.x * blockDim.x + threadIdx.x;
    float* h = (float*)g_hf;
    for (int k = i; k < 3 * 2 * BB * HH; k += gridDim.x * blockDim.x) h[k] = 0.0f;
    if (i == 0) { g_bar_cnt = 0; g_bar_gen = 0; }
}

// ---------------------------------------------------------------------------
// Persistent LSTM: 128 CTAs x 256 threads. CTA nblk owns 8 units
// (uu = nblk*8 + 0..7); its 32 GEMM columns are jj = G*8+u -> row
// r = G*1024 + nblk*8 + u of the [4H, K] weight matrices (read directly).
// Per (t,l): gates[64,32] = [x|h] @ Wslice^T via fp16 mma with in-register
// hi/lo split (3 passes -> fp32-accurate), cell pointwise with c in regs.
// ---------------------------------------------------------------------------
__global__ void __launch_bounds__(256, 1) lstm_persistent(Params p) {
    __shared__ __half Ah[64 * 72];
    __shared__ __half Al[64 * 72];
    __shared__ __half Wh[32 * 72];
    __shared__ __half Wl[32 * 72];
    __shared__ float  Gs[64 * 36];

    const int tid  = threadIdx.x;
    const int lane = tid & 31, warp = tid >> 5;
    const int wm = warp & 1;      // M half: rows wm*32
    const int wn = warp >> 1;     // N-8 block: cols wn*8 (0..3)
    const int grp = lane >> 2, tg = lane & 3;
    const int nblk = blockIdx.x;

    // Load maps
    const int arow = tid >> 2, aq = tid & 3;   // A: 64 rows x 4 quarters(16 k)
    const int wrow = tid >> 3, wq = tid & 7;   // W: 32 rows x 8 octs(8 k)
    const int rload = (wrow >> 3) * HH + nblk * 8 + (wrow & 7);

    // This thread's pointwise ownership: unit u = tid&7, batches b, b+32
    const int u  = tid & 7;
    const int bp = tid >> 3;                   // 0..31
    const int uu = nblk * 8 + u;

    float bias[3][4];
#pragma unroll
    for (int G = 0; G < 4; G++) {
        bias[0][G] = p.bih0[G * HH + uu] + p.bhh0[G * HH + uu];
        bias[1][G] = p.bihr[G * HH + uu] + p.bhhr[G * HH + uu];
        bias[2][G] = p.bihr[4 * HH + G * HH + uu] + p.bhhr[4 * HH + G * HH + uu];
    }
    int len[2] = { p.lengths[bp], p.lengths[bp + 32] };
    float creg[3][2];
#pragma unroll
    for (int l = 0; l < 3; l++) { creg[l][0] = 0.0f; creg[l][1] = 0.0f; }

    unsigned target = 0;

    for (int t = 0; t < TT; t++) {
        const int pin = t & 1, pout = pin ^ 1;
        for (int l = 0; l < 3; l++) {
            const float *A0, *A1, *W0, *W1;
            int astr0, w0str, split, nch;
            if (l == 0) {
                A0 = p.inputs + (size_t)t * BB * VV; astr0 = VV;
                A1 = g_hf[0][pin];
                W0 = p.Wih0; w0str = VV; W1 = p.Whh0;
                split = VV; nch = (VV + HH) / 64;     // 20
            } else if (l == 1) {
                A0 = g_hf[0][pout]; astr0 = HH;
                A1 = g_hf[1][pin];
                W0 = p.Wihr; w0str = HH; W1 = p.Whhr;
                split = HH; nch = 32;
            } else {
                A0 = g_hf[1][pout]; astr0 = HH;
                A1 = g_hf[2][pin];
                W0 = p.Wihr + (size_t)4 * HH * HH; w0str = HH;
                W1 = p.Whhr + (size_t)4 * HH * HH;
                split = HH; nch = 32;
            }

            float acc[2][4];
#pragma unroll
            for (int mi = 0; mi < 2; mi++)
#pragma unroll
                for (int c = 0; c < 4; c++) acc[mi][c] = 0.0f;

            float4 apre[4], wpre[2];
            auto fetch = [&](int c) {
                int k0 = c * 64;
                const float* Ab; const float* Wb; int as, ws, kk;
                if (k0 < split) { Ab = A0; as = astr0; Wb = W0; ws = w0str; kk = k0; }
                else            { Ab = A1; as = HH;    Wb = W1; ws = HH;    kk = k0 - split; }
                const float* ar = Ab + (size_t)arow * as + kk + aq * 16;
                const float* wr = Wb + (size_t)rload * ws + kk + wq * 8;
#pragma unroll
                for (int i = 0; i < 4; i++) apre[i] = __ldcg((const float4*)(ar + i * 4));
#pragma unroll
                for (int i = 0; i < 2; i++) wpre[i] = __ldg((const float4*)(wr + i * 4));
            };
            auto stash = [&]() {
#pragma unroll
                for (int i = 0; i < 4; i++) {
                    float4 v = apre[i];
                    __half hx = __float2half_rn(v.x), hy = __float2half_rn(v.y);
                    __half hz = __float2half_rn(v.z), hw = __float2half_rn(v.w);
                    int o = arow * 72 + aq * 16 + i * 4;
                    *(__half2*)&Ah[o]     = __halves2half2(hx, hy);
                    *(__half2*)&Ah[o + 2] = __halves2half2(hz, hw);
                    *(__half2*)&Al[o]     = __floats2half2_rn(v.x - __half2float(hx),
                                                              v.y - __half2float(hy));
                    *(__half2*)&Al[o + 2] = __floats2half2_rn(v.z - __half2float(hz),
                                                              v.w - __half2float(hw));
                }
#pragma unroll
                for (int i = 0; i < 2; i++) {
                    float4 v = wpre[i];
                    __half hx = __float2half_rn(v.x), hy = __float2half_rn(v.y);
                    __half hz = __float2half_rn(v.z), hw = __float2half_rn(v.w);
                    int o = wrow * 72 + wq * 8 + i * 4;
                    *(__half2*)&Wh[o]     = __halves2half2(hx, hy);
                    *(__half2*)&Wh[o + 2] = __halves2half2(hz, hw);
                    *(__half2*)&Wl[o]     = __floats2half2_rn(v.x - __half2float(hx),
                                                              v.y - __half2float(hy));
                    *(__half2*)&Wl[o + 2] = __floats2half2_rn(v.z - __half2float(hz),
                                                              v.w - __half2float(hw));
                }
            };

            fetch(0);
            for (int c = 0; c < nch; c++) {
                stash();
                __syncthreads();
                if (c + 1 < nch) fetch(c + 1);
#pragma unroll
                for (int kk = 0; kk < 4; kk++) {
                    const int kb = kk * 16 + 2 * tg;
                    uint32_t ah[2][4], al[2][4], whf[2], wlf[2];
#pragma unroll
                    for (int mi = 0; mi < 2; mi++) {
                        int r = wm * 32 + mi * 16 + grp;
                        ah[mi][0] = *(const uint32_t*)(Ah + r * 72 + kb);
                        ah[mi][1] = *(const uint32_t*)(Ah + (r + 8) * 72 + kb);
                        ah[mi][2] = *(const uint32_t*)(Ah + r * 72 + kb + 8);
                        ah[mi][3] = *(const uint32_t*)(Ah + (r + 8) * 72 + kb + 8);
                        al[mi][0] = *(const uint32_t*)(Al + r * 72 + kb);
                        al[mi][1] = *(const uint32_t*)(Al + (r + 8) * 72 + kb);
                        al[mi][2] = *(const uint32_t*)(Al + r * 72 + kb + 8);
                        al[mi][3] = *(const uint32_t*)(Al + (r + 8) * 72 + kb + 8);
                    }
                    {
                        int n = wn * 8 + grp;
                        whf[0] = *(const uint32_t*)(Wh + n * 72 + kb);
                        whf[1] = *(const uint32_t*)(Wh + n * 72 + kb + 8);
                        wlf[0] = *(const uint32_t*)(Wl + n * 72 + kb);
                        wlf[1] = *(const uint32_t*)(Wl + n * 72 + kb + 8);
                    }
#pragma unroll
                    for (int mi = 0; mi < 2; mi++) {
                        mma16816(acc[mi], ah[mi], whf);   // Ahi*Whi
                        mma16816(acc[mi], ah[mi], wlf);   // Ahi*Wlo
                        mma16816(acc[mi], al[mi], whf);   // Alo*Whi
                    }
                }
                __syncthreads();
            }

            // Regroup: warp n-tiles -> per-unit gate columns in smem
#pragma unroll
            for (int mi = 0; mi < 2; mi++) {
                int r = wm * 32 + mi * 16 + grp;
                int cc = wn * 8 + 2 * tg;
                Gs[r * 36 + cc]           = acc[mi][0];
                Gs[r * 36 + cc + 1]       = acc[mi][1];
                Gs[(r + 8) * 36 + cc]     = acc[mi][2];
                Gs[(r + 8) * 36 + cc + 1] = acc[mi][3];
            }
            __syncthreads();

            // Cell pointwise: this thread owns (u, b) and (u, b+32)
            float* hout = g_hf[l][pout];
#pragma unroll
            for (int j = 0; j < 2; j++) {
                int b = bp + j * 32;
                float ii = Gs[b * 36 + u]      + bias[l][0];
                float ff = Gs[b * 36 + 8 + u]  + bias[l][1];
                float gg = Gs[b * 36 + 16 + u] + bias[l][2];
                float oo = Gs[b * 36 + 24 + u] + bias[l][3];
                float cn = sigf(ff) * creg[l][j] + sigf(ii) * tanhf(gg);
                float hn = sigf(oo) * tanhf(cn);
                creg[l][j] = cn;
                size_t ci = (size_t)b * HH + uu;
                __stcg(&hout[ci], hn);
                if (l == 2)
                    g_yT[ci * TT + t] = (t < len[j]) ? hn : 0.0f;
            }
            grid_bar(++target);
        }
    }
}

// ---------------------------------------------------------------------------
// Projection (R10-validated): out[b][v][t] = sum_u Wout[v][u]*yT[b][u][t]+bout[v]
// ---------------------------------------------------------------------------
__global__ void __launch_bounds__(256, 1) proj_kernel(Params p, float* __restrict__ out) {
    __shared__ float Wv[32 * 68];
    __shared__ float Yt[64 * 68];

    const int blk = blockIdx.x;
    const int b  = blk >> 6;
    const int vt = (blk >> 3) & 7;
    const int tt = blk & 7;
    const int tid = threadIdx.x;

    const int yrow = tid >> 2, yq = tid & 3;
    const int wrow = tid >> 3, wq = tid & 7;
    const int vr = tid >> 5;
    const int tc = tid & 31;

    float acc[4][2];
#pragma unroll
    for (int j = 0; j < 4; j++) { acc[j][0] = 0.0f; acc[j][1] = 0.0f; }

    const float* ybase = g_yT + (size_t)b * HH * TT;
    float4 ypre[4], wpre[2];
    auto fetch = [&](int c) {
        int k0 = c * 64;
        const float* yr = ybase + (size_t)(k0 + yrow) * TT + tt * 64 + yq * 16;
#pragma unroll
        for (int i = 0; i < 4; i++) ypre[i] = *(const float4*)(yr + i * 4);
        const float* wr = p.Wout + (size_t)(vt * 32 + wrow) * HH + k0 + wq * 8;
#pragma unroll
        for (int i = 0; i < 2; i++) wpre[i] = *(const float4*)(wr + i * 4);
    };
    auto stash = [&]() {
#pragma unroll
        for (int i = 0; i < 4; i++) *(float4*)&Yt[yrow * 68 + yq * 16 + i * 4] = ypre[i];
#pragma unroll
        for (int i = 0; i < 2; i++) *(float4*)&Wv[wrow * 68 + wq * 8 + i * 4] = wpre[i];
    };

    fetch(0);
    for (int c = 0; c < 16; c++) {
        stash();
        __syncthreads();
        if (c + 1 < 16) fetch(c + 1);
#pragma unroll 8
        for (int k = 0; k < 64; k++) {
            float y0 = Yt[k * 68 + tc * 2];
            float y1 = Yt[k * 68 + tc * 2 + 1];
#pragma unroll
            for (int j = 0; j < 4; j++) {
                float w = Wv[(vr * 4 + j) * 68 + k];
                acc[j][0] += w * y0;
                acc[j][1] += w * y1;
            }
        }
        __syncthreads();
    }

#pragma unroll
    for (int j = 0; j < 4; j++) {
        int v = vt * 32 + vr * 4 + j;
        float bo = p.bout[v];
        size_t o = ((size_t)b * VV + v) * TT + tt * 64 + tc * 2;
        out[o]     = acc[j][0] + bo;
        out[o + 1] = acc[j][1] + bo;
    }
}

// ---------------------------------------------------------------------------
// Launch: 3 graph nodes. Size-based input resolution (R10-validated).
// ---------------------------------------------------------------------------
extern "C" void kernel_launch(void* const* d_in, const int* in_sizes, int n_in,
                              void* d_out, int out_size) {
    Params p = {};
    int nbig = 0, n4k = 0, n8k = 0;
    for (int i = 0; i < n_in; i++) {
        const void* ptr = d_in[i];
        switch (in_sizes[i]) {
            case 8388608:  // inputs / Wih_rest / Whh_rest in dict order
                if (nbig == 0)      p.inputs = (const float*)ptr;
                else if (nbig == 1) p.Wihr   = (const float*)ptr;
                else                p.Whhr   = (const float*)ptr;
                nbig++; break;
            case 64:      p.lengths = (const int*)ptr;   break;
            case 1048576: p.Wih0    = (const float*)ptr; break;
            case 4194304: p.Whh0    = (const float*)ptr; break;
            case 4096:
                if (n4k == 0) p.bih0 = (const float*)ptr; else p.bhh0 = (const float*)ptr;
                n4k++; break;
            case 8192:
                if (n8k == 0) p.bihr = (const float*)ptr; else p.bhhr = (const float*)ptr;
                n8k++; break;
            case 262144:  p.Wout = (const float*)ptr; break;
            case 256:     p.bout = (const float*)ptr; break;
            default: break;
        }
    }

    init_kernel<<<256, 256>>>();
    lstm_persistent<<<NCTA, 256>>>(p);
    proj_kernel<<<64 * 8 * 8, 256>>>(p, (float*)d_out);
}